// round 8
// baseline (speedup 1.0000x reference)
#include <cuda_runtime.h>
#include <cuda_fp16.h>
#include <math.h>

#define NN 20000
#define EE 320000
#define ET (EE + NN)
#define GG 64
#define FULL 0xffffffffu
#define GEMM_BLOCKS 625                   // 5000 warps / 8 per block
#define COUNT_BLOCKS ((EE / 4 + 255) / 256)

// ---------------- scratch ----------------
__device__ __half g_h[NN * 256];
__device__ __half g_h2[NN * 64];
__device__ float g_asrc[NN * 4];
__device__ float g_adst[NN * 4];
__device__ float g_asrc2[NN * 2];
__device__ float g_adst2[NN * 2];
__device__ int   g_cnt[NN];
__device__ int   g_off[NN + 1];
__device__ int   g_cur[NN];
__device__ int   g_csr[ET];
__device__ float g_sums[GG * 32];
__device__ float g_gcnt[GG];

__device__ __forceinline__ float lrelu(float v) { return v > 0.f ? v : 0.2f * v; }
__device__ __forceinline__ float warp_sum(float v) {
#pragma unroll
    for (int o = 16; o > 0; o >>= 1) v += __shfl_xor_sync(FULL, v, o);
    return v;
}

// packed f32x2 helpers
#define SPLAT2(out, f) asm("mov.b64 %0, {%1, %1};" : "=l"(out) : "r"(__float_as_uint(f)))
#define FMA2(acc, a, b) asm("fma.rn.f32x2 %0, %1, %2, %0;" : "+l"(acc) : "l"(a), "l"(b))
#define UNPACK2(lo, hi, in) asm("mov.b64 {%0, %1}, %2;" : "=r"(lo), "=r"(hi) : "l"(in))

// ---------------- scan (+1 self-loop; zero pooling buffers) ----------------
__global__ void k_scan(const int* __restrict__ cnt, int* __restrict__ off,
                       int* __restrict__ cur, float* __restrict__ sums,
                       float* __restrict__ gcnt) {
    __shared__ int ssum[1024];
    const int CH = 20;
    int t = threadIdx.x;
    sums[t] = 0.f; sums[t + 1024] = 0.f;
    if (t < GG) gcnt[t] = 0.f;
    int base = t * CH;
    int local[CH];
    int s = 0;
#pragma unroll
    for (int j = 0; j < CH; j++) {
        int v = (base + j < NN) ? (cnt[base + j] + 1) : 0;
        local[j] = s;
        s += v;
    }
    ssum[t] = s;
    __syncthreads();
    for (int o = 1; o < 1024; o <<= 1) {
        int v = (t >= o) ? ssum[t - o] : 0;
        __syncthreads();
        ssum[t] += v;
        __syncthreads();
    }
    int pre = ssum[t] - s;
#pragma unroll
    for (int j = 0; j < CH; j++) {
        if (base + j < NN) { off[base + j] = pre + local[j]; cur[base + j] = pre + local[j]; }
    }
    if (t == 1023) off[NN] = ssum[1023];
}

// ---------------- CSR fill ----------------
__global__ void k_build(const int* __restrict__ src, const int* __restrict__ dst,
                        int* __restrict__ cur, int* __restrict__ csr) {
    int t = blockIdx.x * blockDim.x + threadIdx.x;
    if (t < EE / 4) {
        int4 s4 = ((const int4*)src)[t];
        int4 d4 = ((const int4*)dst)[t];
        csr[atomicAdd(&cur[d4.x], 1)] = s4.x;
        csr[atomicAdd(&cur[d4.y], 1)] = s4.y;
        csr[atomicAdd(&cur[d4.z], 1)] = s4.z;
        csr[atomicAdd(&cur[d4.w], 1)] = s4.w;
    } else {
        int n = t - EE / 4;
        if (n < NN) csr[atomicAdd(&cur[n], 1)] = n;
    }
}

// ---------------- GEMM1 (fp32 in, fp16 out) + att1 + fused degree count ----
__global__ void k_gemm1_count(const float* __restrict__ A, const float* __restrict__ B,
                              const float* __restrict__ as1, const float* __restrict__ ad1,
                              __half* __restrict__ C, float* __restrict__ asrc,
                              float* __restrict__ adst,
                              const int* __restrict__ dst, int* __restrict__ cnt) {
    if (blockIdx.x >= GEMM_BLOCKS) {
        int t = (blockIdx.x - GEMM_BLOCKS) * blockDim.x + threadIdx.x;
        if (t < EE / 4) {
            int4 d4 = ((const int4*)dst)[t];
            atomicAdd(&cnt[d4.x], 1);
            atomicAdd(&cnt[d4.y], 1);
            atomicAdd(&cnt[d4.z], 1);
            atomicAdd(&cnt[d4.w], 1);
        }
        return;
    }

    int gw = blockIdx.x * 8 + (threadIdx.x >> 5);
    int lane = threadIdx.x & 31;
    int strip = gw >> 1;
    int half_ = gw & 1;
    int cg = half_ * 32 + lane;
    int row0 = strip * 8;

    const float4* A4 = (const float4*)A;
    const ulonglong2* B2 = (const ulonglong2*)B + cg;

    unsigned long long acc[8][2];
#pragma unroll
    for (int r = 0; r < 8; r++) { acc[r][0] = 0ull; acc[r][1] = 0ull; }

#pragma unroll 2
    for (int i = 0; i < 32; i++) {
        ulonglong2 b0 = B2[(4 * i + 0) * 64];
        ulonglong2 b1 = B2[(4 * i + 1) * 64];
        ulonglong2 b2 = B2[(4 * i + 2) * 64];
        ulonglong2 b3 = B2[(4 * i + 3) * 64];
#pragma unroll
        for (int r = 0; r < 8; r++) {
            float4 a = A4[(row0 + r) * 32 + i];
            unsigned long long ax, ay, az, aw;
            SPLAT2(ax, a.x); SPLAT2(ay, a.y); SPLAT2(az, a.z); SPLAT2(aw, a.w);
            FMA2(acc[r][0], ax, b0.x); FMA2(acc[r][1], ax, b0.y);
            FMA2(acc[r][0], ay, b1.x); FMA2(acc[r][1], ay, b1.y);
            FMA2(acc[r][0], az, b2.x); FMA2(acc[r][1], az, b2.y);
            FMA2(acc[r][0], aw, b3.x); FMA2(acc[r][1], aw, b3.y);
        }
    }

    float4 av = ((const float4*)as1)[cg];
    float4 dv = ((const float4*)ad1)[cg];
    uint2* C2 = (uint2*)C;
    float s[8], dd[8];
#pragma unroll
    for (int r = 0; r < 8; r++) {
        float4 c;
        unsigned int lo, hi;
        UNPACK2(lo, hi, acc[r][0]); c.x = __uint_as_float(lo); c.y = __uint_as_float(hi);
        UNPACK2(lo, hi, acc[r][1]); c.z = __uint_as_float(lo); c.w = __uint_as_float(hi);
        half2 p0 = __floats2half2_rn(c.x, c.y);
        half2 p1 = __floats2half2_rn(c.z, c.w);
        uint2 pk;
        pk.x = *(unsigned int*)&p0;
        pk.y = *(unsigned int*)&p1;
        C2[(row0 + r) * 64 + cg] = pk;
        s[r]  = c.x * av.x + c.y * av.y + c.z * av.z + c.w * av.w;
        dd[r] = c.x * dv.x + c.y * dv.y + c.z * dv.z + c.w * dv.w;
    }
#pragma unroll
    for (int o = 1; o < 16; o <<= 1) {
#pragma unroll
        for (int r = 0; r < 8; r++) {
            s[r]  += __shfl_xor_sync(FULL, s[r], o);
            dd[r] += __shfl_xor_sync(FULL, dd[r], o);
        }
    }
    if ((lane & 15) == 0) {
        int head = cg >> 4;
#pragma unroll
        for (int r = 0; r < 8; r++) {
            asrc[(row0 + r) * 4 + head] = s[r];
            adst[(row0 + r) * 4 + head] = dd[r];
        }
    }
}

// ---------------- layer 1 aggregation: single-pass, MLP-unrolled gather ----
__global__ void k_agg1(const int* __restrict__ off, const int* __restrict__ csr,
                       const __half* __restrict__ hfeat, const float* __restrict__ asrc,
                       const float* __restrict__ adst, const float* __restrict__ bias,
                       const float* __restrict__ W2, const float* __restrict__ as2,
                       const float* __restrict__ ad2, __half* __restrict__ h2out,
                       float* __restrict__ asrc2, float* __restrict__ adst2) {
    __shared__ int    sm_s[8][32];
    __shared__ float4 sm_w[8][32];
    int wid = threadIdx.x >> 5;
    int lane = threadIdx.x & 31;
    int d = blockIdx.x * 8 + wid;
    if (d >= NN) return;
    int b0 = off[d], b1 = off[d + 1];

    float4 adv = ((const float4*)adst)[d];
    int hh = lane >> 3;

    float s0 = 0.f, s1 = 0.f, s2 = 0.f, s3 = 0.f;
    float acc[8];
#pragma unroll
    for (int j = 0; j < 8; j++) acc[j] = 0.f;

    const uint4* hf = (const uint4*)hfeat;
    const float4* as4 = (const float4*)asrc;
    const float* wp = (const float*)&sm_w[wid][0];

    for (int base = b0; base < b1; base += 32) {
        int k = base + lane;
        float4 w = make_float4(0.f, 0.f, 0.f, 0.f);
        int sidx = 0;
        if (k < b1) {
            sidx = csr[k];
            float4 a = as4[sidx];
            w.x = __expf(lrelu(a.x + adv.x));
            w.y = __expf(lrelu(a.y + adv.y));
            w.z = __expf(lrelu(a.z + adv.z));
            w.w = __expf(lrelu(a.w + adv.w));
            s0 += w.x; s1 += w.y; s2 += w.z; s3 += w.w;
        }
        sm_s[wid][lane] = sidx;
        sm_w[wid][lane] = w;
        __syncwarp();
        int cnt = min(32, b1 - base);
        int e = 0;
        // unroll-2: two independent row gathers in flight
        for (; e + 2 <= cnt; e += 2) {
            int ss0 = sm_s[wid][e];
            int ss1 = sm_s[wid][e + 1];
            float w0 = wp[e * 4 + hh];
            float w1 = wp[(e + 1) * 4 + hh];
            uint4 v0 = hf[ss0 * 32 + lane];
            uint4 v1 = hf[ss1 * 32 + lane];
            float2 p;
            p = __half22float2(*(half2*)&v0.x); acc[0] = fmaf(w0, p.x, acc[0]); acc[1] = fmaf(w0, p.y, acc[1]);
            p = __half22float2(*(half2*)&v0.y); acc[2] = fmaf(w0, p.x, acc[2]); acc[3] = fmaf(w0, p.y, acc[3]);
            p = __half22float2(*(half2*)&v0.z); acc[4] = fmaf(w0, p.x, acc[4]); acc[5] = fmaf(w0, p.y, acc[5]);
            p = __half22float2(*(half2*)&v0.w); acc[6] = fmaf(w0, p.x, acc[6]); acc[7] = fmaf(w0, p.y, acc[7]);
            p = __half22float2(*(half2*)&v1.x); acc[0] = fmaf(w1, p.x, acc[0]); acc[1] = fmaf(w1, p.y, acc[1]);
            p = __half22float2(*(half2*)&v1.y); acc[2] = fmaf(w1, p.x, acc[2]); acc[3] = fmaf(w1, p.y, acc[3]);
            p = __half22float2(*(half2*)&v1.z); acc[4] = fmaf(w1, p.x, acc[4]); acc[5] = fmaf(w1, p.y, acc[5]);
            p = __half22float2(*(half2*)&v1.w); acc[6] = fmaf(w1, p.x, acc[6]); acc[7] = fmaf(w1, p.y, acc[7]);
        }
        if (e < cnt) {
            int ss0 = sm_s[wid][e];
            float w0 = wp[e * 4 + hh];
            uint4 v0 = hf[ss0 * 32 + lane];
            float2 p;
            p = __half22float2(*(half2*)&v0.x); acc[0] = fmaf(w0, p.x, acc[0]); acc[1] = fmaf(w0, p.y, acc[1]);
            p = __half22float2(*(half2*)&v0.y); acc[2] = fmaf(w0, p.x, acc[2]); acc[3] = fmaf(w0, p.y, acc[3]);
            p = __half22float2(*(half2*)&v0.z); acc[4] = fmaf(w0, p.x, acc[4]); acc[5] = fmaf(w0, p.y, acc[5]);
            p = __half22float2(*(half2*)&v0.w); acc[6] = fmaf(w0, p.x, acc[6]); acc[7] = fmaf(w0, p.y, acc[7]);
        }
        __syncwarp();
    }

    s0 = warp_sum(s0); s1 = warp_sum(s1); s2 = warp_sum(s2); s3 = warp_sum(s3);
    float iH = (hh == 0) ? 1.f / (s0 + 1e-16f)
             : (hh == 1) ? 1.f / (s1 + 1e-16f)
             : (hh == 2) ? 1.f / (s2 + 1e-16f)
             :             1.f / (s3 + 1e-16f);
#pragma unroll
    for (int j = 0; j < 8; j++) acc[j] *= iH;

#pragma unroll
    for (int j = 0; j < 8; j++) {
        acc[j] += __shfl_xor_sync(FULL, acc[j], 8);
        acc[j] += __shfl_xor_sync(FULL, acc[j], 16);
    }
    int cq = lane & 7;
    float4 bb0 = ((const float4*)bias)[cq * 2];
    float4 bb1 = ((const float4*)bias)[cq * 2 + 1];
    float xv[8];
    xv[0] = fmaxf(acc[0] * 0.25f + bb0.x, 0.f);
    xv[1] = fmaxf(acc[1] * 0.25f + bb0.y, 0.f);
    xv[2] = fmaxf(acc[2] * 0.25f + bb0.z, 0.f);
    xv[3] = fmaxf(acc[3] * 0.25f + bb0.w, 0.f);
    xv[4] = fmaxf(acc[4] * 0.25f + bb1.x, 0.f);
    xv[5] = fmaxf(acc[5] * 0.25f + bb1.y, 0.f);
    xv[6] = fmaxf(acc[6] * 0.25f + bb1.z, 0.f);
    xv[7] = fmaxf(acc[7] * 0.25f + bb1.w, 0.f);

    const float2* W2f2 = (const float2*)W2;
    float2 h2 = make_float2(0.f, 0.f);
#pragma unroll
    for (int g = 0; g < 8; g++) {
#pragma unroll
        for (int j = 0; j < 8; j++) {
            float v = __shfl_sync(FULL, xv[j], g);
            float2 w = W2f2[(8 * g + j) * 32 + lane];
            h2.x = fmaf(v, w.x, h2.x);
            h2.y = fmaf(v, w.y, h2.y);
        }
    }
    half2 h2h = __floats2half2_rn(h2.x, h2.y);
    ((half2*)h2out)[d * 32 + lane] = h2h;

    float2 a2 = ((const float2*)as2)[lane];
    float2 d2 = ((const float2*)ad2)[lane];
    float ps = h2.x * a2.x + h2.y * a2.y;
    float pd = h2.x * d2.x + h2.y * d2.y;
#pragma unroll
    for (int o = 1; o < 16; o <<= 1) {
        ps += __shfl_xor_sync(FULL, ps, o);
        pd += __shfl_xor_sync(FULL, pd, o);
    }
    if ((lane & 15) == 0) {
        asrc2[d * 2 + (lane >> 4)] = ps;
        adst2[d * 2 + (lane >> 4)] = pd;
    }
}

// ---------------- layer 2 aggregation: single-pass, unroll-4 + pool --------
__global__ void k_agg2(const int* __restrict__ off, const int* __restrict__ csr,
                       const __half* __restrict__ hfeat, const float* __restrict__ asrc,
                       const float* __restrict__ adst, const float* __restrict__ bias,
                       const int* __restrict__ batch, float* __restrict__ sums,
                       float* __restrict__ gcnt) {
    __shared__ int    sm_s[8][32];
    __shared__ float2 sm_w[8][32];
    int wid = threadIdx.x >> 5;
    int lane = threadIdx.x & 31;
    int d = blockIdx.x * 8 + wid;
    if (d >= NN) return;
    int b0 = off[d], b1 = off[d + 1];

    float2 adv = ((const float2*)adst)[d];
    int hh = lane >> 4;

    float s0 = 0.f, s1 = 0.f;
    float2 acc = make_float2(0.f, 0.f);
    const half2* hf = (const half2*)hfeat;
    const float2* as2p = (const float2*)asrc;
    const float* wp = (const float*)&sm_w[wid][0];

    for (int base = b0; base < b1; base += 32) {
        int k = base + lane;
        float2 w = make_float2(0.f, 0.f);
        int sidx = 0;
        if (k < b1) {
            sidx = csr[k];
            float2 a = as2p[sidx];
            w.x = __expf(lrelu(a.x + adv.x));
            w.y = __expf(lrelu(a.y + adv.y));
            s0 += w.x; s1 += w.y;
        }
        sm_s[wid][lane] = sidx;
        sm_w[wid][lane] = w;
        __syncwarp();
        int cnt = min(32, b1 - base);
        int e = 0;
        for (; e + 4 <= cnt; e += 4) {
            int ss0 = sm_s[wid][e];
            int ss1 = sm_s[wid][e + 1];
            int ss2 = sm_s[wid][e + 2];
            int ss3 = sm_s[wid][e + 3];
            float w0 = wp[(e + 0) * 2 + hh];
            float w1 = wp[(e + 1) * 2 + hh];
            float w2 = wp[(e + 2) * 2 + hh];
            float w3 = wp[(e + 3) * 2 + hh];
            float2 v0 = __half22float2(hf[ss0 * 32 + lane]);
            float2 v1 = __half22float2(hf[ss1 * 32 + lane]);
            float2 v2 = __half22float2(hf[ss2 * 32 + lane]);
            float2 v3 = __half22float2(hf[ss3 * 32 + lane]);
            acc.x = fmaf(w0, v0.x, acc.x); acc.y = fmaf(w0, v0.y, acc.y);
            acc.x = fmaf(w1, v1.x, acc.x); acc.y = fmaf(w1, v1.y, acc.y);
            acc.x = fmaf(w2, v2.x, acc.x); acc.y = fmaf(w2, v2.y, acc.y);
            acc.x = fmaf(w3, v3.x, acc.x); acc.y = fmaf(w3, v3.y, acc.y);
        }
        for (; e < cnt; e++) {
            int ss = sm_s[wid][e];
            float we = wp[e * 2 + hh];
            float2 v = __half22float2(hf[ss * 32 + lane]);
            acc.x = fmaf(we, v.x, acc.x);
            acc.y = fmaf(we, v.y, acc.y);
        }
        __syncwarp();
    }

    s0 = warp_sum(s0); s1 = warp_sum(s1);
    float iH = hh ? 1.f / (s1 + 1e-16f) : 1.f / (s0 + 1e-16f);
    acc.x *= iH;
    acc.y *= iH;

    acc.x += __shfl_xor_sync(FULL, acc.x, 16);
    acc.y += __shfl_xor_sync(FULL, acc.y, 16);
    if (lane < 16) {
        const float2 b = ((const float2*)bias)[lane];
        float ox = fmaxf(acc.x * 0.5f + b.x, 0.f);
        float oy = fmaxf(acc.y * 0.5f + b.y, 0.f);
        int g = batch[d];
        atomicAdd(&sums[g * 32 + 2 * lane], ox);
        atomicAdd(&sums[g * 32 + 2 * lane + 1], oy);
        if (lane == 0) atomicAdd(&gcnt[g], 1.f);
    }
}

// ---------------- heads ----------------
__global__ void k_heads(const float* __restrict__ sums, const float* __restrict__ cnt,
                        const float* __restrict__ cW1, const float* __restrict__ cb1,
                        const float* __restrict__ cW2, const float* __restrict__ cb2,
                        const float* __restrict__ hW1, const float* __restrict__ hb1,
                        const float* __restrict__ hW2, const float* __restrict__ hb2,
                        float* __restrict__ out) {
    int g = threadIdx.x;
    if (g >= GG) return;
    float emb[32];
    float c_ = cnt[g];
    c_ = (c_ > 1.f) ? c_ : 1.f;
    for (int c = 0; c < 32; c++) emb[c] = sums[g * 32 + c] / c_;
    float oh = hb2[0], oc = cb2[0];
    for (int j = 0; j < 16; j++) {
        float sh = hb1[j], sc = cb1[j];
        for (int c = 0; c < 32; c++) {
            sh = fmaf(emb[c], hW1[c * 16 + j], sh);
            sc = fmaf(emb[c], cW1[c * 16 + j], sc);
        }
        sh = fmaxf(sh, 0.f);
        sc = fmaxf(sc, 0.f);
        oh = fmaf(sh, hW2[j], oh);
        oc = fmaf(sc, cW2[j], oc);
    }
    out[g]      = 1.f / (1.f + __expf(-oh));
    out[GG + g] = 1.f / (1.f + __expf(-oc));
}

// ---------------- host ----------------
static inline int cdiv(long long a, int b) { return (int)((a + b - 1) / b); }

extern "C" void kernel_launch(void* const* d_in, const int* in_sizes, int n_in,
                              void* d_out, int out_size) {
    const float* x     = (const float*)d_in[0];
    const int*   ei    = (const int*)  d_in[1];
    const int*   batch = (const int*)  d_in[2];
    const float* W1  = (const float*)d_in[3];
    const float* as1 = (const float*)d_in[4];
    const float* ad1 = (const float*)d_in[5];
    const float* b1  = (const float*)d_in[6];
    const float* W2  = (const float*)d_in[7];
    const float* as2 = (const float*)d_in[8];
    const float* ad2 = (const float*)d_in[9];
    const float* b2  = (const float*)d_in[10];
    const float* cW1 = (const float*)d_in[11];
    const float* cb1 = (const float*)d_in[12];
    const float* cW2 = (const float*)d_in[13];
    const float* cb2 = (const float*)d_in[14];
    const float* hW1 = (const float*)d_in[15];
    const float* hb1 = (const float*)d_in[16];
    const float* hW2 = (const float*)d_in[17];
    const float* hb2 = (const float*)d_in[18];

    const int* src = ei;
    const int* dst = ei + EE;

    __half *p_h, *p_h2;
    float *p_asrc, *p_adst, *p_asrc2, *p_adst2, *p_sums, *p_gcnt;
    int *p_cnt, *p_off, *p_cur, *p_csr;
    cudaGetSymbolAddress((void**)&p_h, g_h);
    cudaGetSymbolAddress((void**)&p_h2, g_h2);
    cudaGetSymbolAddress((void**)&p_asrc, g_asrc);
    cudaGetSymbolAddress((void**)&p_adst, g_adst);
    cudaGetSymbolAddress((void**)&p_asrc2, g_asrc2);
    cudaGetSymbolAddress((void**)&p_adst2, g_adst2);
    cudaGetSymbolAddress((void**)&p_cnt, g_cnt);
    cudaGetSymbolAddress((void**)&p_off, g_off);
    cudaGetSymbolAddress((void**)&p_cur, g_cur);
    cudaGetSymbolAddress((void**)&p_csr, g_csr);
    cudaGetSymbolAddress((void**)&p_sums, g_sums);
    cudaGetSymbolAddress((void**)&p_gcnt, g_gcnt);

    const int T = 256;

    cudaMemsetAsync(p_cnt, 0, NN * sizeof(int));
    k_gemm1_count<<<GEMM_BLOCKS + COUNT_BLOCKS, T>>>(x, W1, as1, ad1, p_h,
                                                     p_asrc, p_adst, dst, p_cnt);
    k_scan<<<1, 1024>>>(p_cnt, p_off, p_cur, p_sums, p_gcnt);
    k_build<<<cdiv(EE / 4 + NN, T), T>>>(src, dst, p_cur, p_csr);

    k_agg1<<<cdiv(NN, 8), T>>>(p_off, p_csr, p_h, p_asrc, p_adst, b1,
                               W2, as2, ad2, p_h2, p_asrc2, p_adst2);
    k_agg2<<<cdiv(NN, 8), T>>>(p_off, p_csr, p_h2, p_asrc2, p_adst2, b2,
                               batch, p_sums, p_gcnt);
    k_heads<<<1, GG>>>(p_sums, p_gcnt, cW1, cb1, cW2, cb2, hW1, hb1, hW2, hb2,
                       (float*)d_out);
}